// round 15
// baseline (speedup 1.0000x reference)
#include <cuda_runtime.h>
#include <cuda_fp16.h>
#include <math.h>
#include <stdint.h>

#define BB 4
#define SS 4096
#define DD 512

// ---------------- scratch (static device globals) ----------------
__device__ __half g_t   [BB * SS * DD];            // token fp16
__device__ __half g_w12h[2 * DD * DD];             // [W1; W2] rows 0..1023
__device__ __half g_w3h [DD * DD];
__device__ __half g_qk  [BB * SS * 2 * DD];        // [16384, 1024]: Q | K
__device__ __half g_vt  [DD * BB * SS];            // V^T [DD, BB*SS]
__device__ __half g_s   [(size_t)BB * SS * SS];    // E = exp(logit*scale), fp16
__device__ float  g_rs  [BB * SS];                 // per-row sums of E

// ---------------- PTX helpers (baseline ISA, sm_80-class) ----------------
__device__ __forceinline__ uint32_t smem_u32(const void* p) {
    return (uint32_t)__cvta_generic_to_shared(p);
}
__device__ __forceinline__ void cp_async16(uint32_t s, const void* g) {
    asm volatile("cp.async.cg.shared.global [%0], [%1], 16;" :: "r"(s), "l"(g));
}
__device__ __forceinline__ void cp_commit() {
    asm volatile("cp.async.commit_group;" ::: "memory");
}
template <int N>
__device__ __forceinline__ void cp_wait() {
    asm volatile("cp.async.wait_group %0;" :: "n"(N) : "memory");
}
__device__ __forceinline__ void ldsm4(uint32_t* r, uint32_t addr) {
    asm volatile("ldmatrix.sync.aligned.m8n8.x4.shared.b16 {%0,%1,%2,%3}, [%4];"
                 : "=r"(r[0]), "=r"(r[1]), "=r"(r[2]), "=r"(r[3]) : "r"(addr));
}
__device__ __forceinline__ void mma16816(float* d, const uint32_t* a, uint32_t b0, uint32_t b1) {
    asm volatile("mma.sync.aligned.m16n8k16.row.col.f32.f16.f16.f32 "
                 "{%0,%1,%2,%3}, {%4,%5,%6,%7}, {%8,%9}, {%0,%1,%2,%3};"
                 : "+f"(d[0]), "+f"(d[1]), "+f"(d[2]), "+f"(d[3])
                 : "r"(a[0]), "r"(a[1]), "r"(a[2]), "r"(a[3]), "r"(b0), "r"(b1));
}

// KCH=64: row = 128 B = 8 chunks of 16 B; swizzle chunk ^ (row&7)
#define KCH 64
#define TILE_BYTES (128 * KCH * 2)          // 16 KB
#define STAGE_BYTES (2 * TILE_BYTES)        // A + B = 32 KB
#define NSTAGE 3
#define SMEM_BYTES (NSTAGE * STAGE_BYTES)   // 96 KB -> 2 CTAs/SM

__device__ __forceinline__ uint32_t swz(int row, int chunk) {
    return (uint32_t)(row * 128 + (((chunk ^ (row & 7)) & 7) << 4));
}

// ---------------------------------------------------------------------------
// single-fp16 NT GEMM on HMMA: C[m,n] = sum_k A[m,k]*B[n,k]
// OUTMODE 1: fp32 C divided by rowsum   (PV)
// OUTMODE 2: fp16 C                     (projections)
// OUTMODE 3: fp16 exp(C*scale) + atomic row sums  (QK^T)
// Epilogue staged through smem for fully-coalesced 16B stores.
// M,N multiples of 128; K multiple of 64.
// ---------------------------------------------------------------------------
template <int OUTMODE>
__global__ __launch_bounds__(256, 2)
void mma_gemm(const __half* __restrict__ As, int lda, long long sA,
              const __half* __restrict__ Bs, int ldb, long long sB,
              float* __restrict__ Cf, __half* __restrict__ Ch,
              float* __restrict__ Rs,
              int ldc, long long sC, int K)
{
    extern __shared__ __align__(1024) char smem[];
    const int tid  = threadIdx.x;
    const int wid  = tid >> 5;
    const int lane = tid & 31;

    const long long zz = blockIdx.z;
    const __half* pA = As + zz * sA;
    const __half* pB = Bs + zz * sB;

    const int m0 = blockIdx.y * 128;
    const int n0 = blockIdx.x * 128;

    uint32_t s_off[4];
    int g_row[4], g_col[4];
#pragma unroll
    for (int i = 0; i < 4; i++) {
        const int idx = tid + (i << 8);
        const int row = idx >> 3;
        const int c   = idx & 7;
        s_off[i] = swz(row, c);
        g_row[i] = row;
        g_col[i] = c * 8;
    }

    const int nkt = K / KCH;

    auto load_stage = [&](int kt) {
        const uint32_t sb32 = smem_u32(smem) + (uint32_t)((kt % NSTAGE) * STAGE_BYTES);
        const int kb = kt * KCH;
#pragma unroll
        for (int i = 0; i < 4; i++) {
            const long long ga = (long long)(m0 + g_row[i]) * lda + kb + g_col[i];
            const long long gb = (long long)(n0 + g_row[i]) * ldb + kb + g_col[i];
            cp_async16(sb32 + s_off[i],              pA + ga);
            cp_async16(sb32 + TILE_BYTES + s_off[i], pB + gb);
        }
        cp_commit();
    };

    float acc[4][4][4];
#pragma unroll
    for (int a = 0; a < 4; a++)
#pragma unroll
        for (int b = 0; b < 4; b++)
#pragma unroll
            for (int c = 0; c < 4; c++) acc[a][b][c] = 0.0f;

    const int wm = wid >> 2;
    const int wn = wid & 3;
    const int r8 = lane & 7;
    const int aRowSel = (lane >> 3) & 1;
    const int aChkSel = (lane >> 4) & 1;
    const int bRowSel = (lane >> 4) & 1;
    const int bChkSel = (lane >> 3) & 1;

    load_stage(0);
    load_stage(1);

    for (int kt = 0; kt < nkt; kt++) {
        if (kt + 1 < nkt) cp_wait<1>();
        else              cp_wait<0>();
        __syncthreads();
        if (kt + 2 < nkt) load_stage(kt + 2);

        const uint32_t aB = smem_u32(smem) + (uint32_t)((kt % NSTAGE) * STAGE_BYTES);
        const uint32_t bB = aB + TILE_BYTES;

#pragma unroll
        for (int h = 0; h < KCH / 16; h++) {
            const int kc = 2 * h;
            uint32_t bfr[8];
#pragma unroll
            for (int p = 0; p < 2; p++) {
                const int brow = wn * 32 + p * 16 + bRowSel * 8 + r8;
                const uint32_t ad = bB + swz(brow, kc + bChkSel);
                ldsm4(&bfr[p * 4], ad);
            }
#pragma unroll
            for (int mt = 0; mt < 4; mt++) {
                const int arow = wm * 64 + mt * 16 + aRowSel * 8 + r8;
                const uint32_t ad = aB + swz(arow, kc + aChkSel);
                uint32_t ah[4];
                ldsm4(ah, ad);
#pragma unroll
                for (int nt = 0; nt < 4; nt++) {
                    const int p  = nt >> 1;
                    const int of = (nt & 1) * 2;
                    mma16816(acc[mt][nt], ah, bfr[p * 4 + of], bfr[p * 4 + of + 1]);
                }
            }
        }
    }

    // ---------------- epilogue (smem-staged, coalesced stores) ----------------
    __syncthreads();                       // mainloop smem no longer needed
    char* wsm = smem + 65536 + wid * 2560; // per-warp staging (region 2)
    const int er = (lane >> 2);
    const int ec = (lane & 3) * 2;
    const float scale = 0.04419417382415922f; // 1/sqrt(512)
    const int lr = lane >> 1;
    const int hf = lane & 1;

#pragma unroll
    for (int mt = 0; mt < 4; mt++) {
        const int rbase = m0 + wm * 64 + mt * 16;
        float invl = 1.0f, invh = 1.0f;
        if (OUTMODE == 1) {
            invl = 1.0f / Rs[zz * SS + rbase + er];
            invh = 1.0f / Rs[zz * SS + rbase + er + 8];
        }
        float sl = 0.0f, sh = 0.0f;
#pragma unroll
        for (int nt = 0; nt < 4; nt++) {
            float* a = acc[mt][nt];
            if (OUTMODE == 1) {
                *(float2*)(wsm + er * 160 + nt * 32 + ec * 4)       = make_float2(a[0] * invl, a[1] * invl);
                *(float2*)(wsm + (er + 8) * 160 + nt * 32 + ec * 4) = make_float2(a[2] * invh, a[3] * invh);
            } else if (OUTMODE == 2) {
                __half2 v0, v1;
                v0.x = __float2half_rn(a[0]); v0.y = __float2half_rn(a[1]);
                v1.x = __float2half_rn(a[2]); v1.y = __float2half_rn(a[3]);
                *(__half2*)(wsm + er * 80 + nt * 16 + ec * 2)       = v0;
                *(__half2*)(wsm + (er + 8) * 80 + nt * 16 + ec * 2) = v1;
            } else { // OUTMODE 3
                float e0 = __expf(fminf(a[0] * scale, 10.0f));
                float e1 = __expf(fminf(a[1] * scale, 10.0f));
                float e2 = __expf(fminf(a[2] * scale, 10.0f));
                float e3 = __expf(fminf(a[3] * scale, 10.0f));
                sl += e0 + e1;
                sh += e2 + e3;
                __half2 v0, v1;
                v0.x = __float2half_rn(e0); v0.y = __float2half_rn(e1);
                v1.x = __float2half_rn(e2); v1.y = __float2half_rn(e3);
                *(__half2*)(wsm + er * 80 + nt * 16 + ec * 2)       = v0;
                *(__half2*)(wsm + (er + 8) * 80 + nt * 16 + ec * 2) = v1;
            }
        }
        if (OUTMODE == 3) {
            sl += __shfl_xor_sync(0xffffffffu, sl, 1);
            sl += __shfl_xor_sync(0xffffffffu, sl, 2);
            sh += __shfl_xor_sync(0xffffffffu, sh, 1);
            sh += __shfl_xor_sync(0xffffffffu, sh, 2);
            if ((lane & 3) == 0) {
                atomicAdd(Rs + zz * SS + rbase + er,     sl);
                atomicAdd(Rs + zz * SS + rbase + er + 8, sh);
            }
        }
        __syncwarp();
        // coalesced flush: 2 lanes per row
        const int grow = rbase + lr;
        if (OUTMODE == 1) {
            float* dst = Cf + zz * sC + (long long)grow * ldc + n0 + wn * 32 + hf * 16;
            const uint4* src = (const uint4*)(wsm + lr * 160 + hf * 64);
#pragma unroll
            for (int j = 0; j < 4; j++)
                *(uint4*)(dst + j * 4) = src[j];
        } else {
            __half* dst = Ch + zz * sC + (long long)grow * ldc + n0 + wn * 32 + hf * 16;
            const uint4* src = (const uint4*)(wsm + lr * 80 + hf * 32);
            *(uint4*)(dst)     = src[0];
            *(uint4*)(dst + 8) = src[1];
        }
        __syncwarp();
    }
}

// ---------------------------------------------------------------------------
// all conversions in one launch: token -> fp16, W1/W2 -> w12h, W3 -> w3h,
// plus zeroing of the rowsum buffer (tail blocks).
// ---------------------------------------------------------------------------
#define TOK_N4 (BB * SS * DD / 4)
#define W_N4   (DD * DD / 4)
#define RS_N4  (BB * SS / 4)
__global__ __launch_bounds__(256)
void conv_kernel(const float* __restrict__ token,
                 const float* __restrict__ W1, const float* __restrict__ W2,
                 const float* __restrict__ W3,
                 __half* __restrict__ th, __half* __restrict__ w12h,
                 __half* __restrict__ w3h, float* __restrict__ rs)
{
    const int gi = blockIdx.x * 256 + threadIdx.x;
    if (gi >= TOK_N4 + 3 * W_N4) {
        const int i = gi - (TOK_N4 + 3 * W_N4);
        if (i < RS_N4) ((float4*)rs)[i] = make_float4(0.f, 0.f, 0.f, 0.f);
        return;
    }
    const float* src;
    __half* dst;
    int i;
    if (gi < TOK_N4) { src = token; dst = th; i = gi; }
    else {
        const int r = gi - TOK_N4;
        const int which = r / W_N4;
        i = r - which * W_N4;
        src = (which == 0) ? W1 : (which == 1) ? W2 : W3;
        dst = (which == 0) ? w12h : (which == 1) ? (w12h + DD * DD) : w3h;
    }
    float4 v = ((const float4*)src)[i];
    __half2 a, b;
    a.x = __float2half_rn(v.x); a.y = __float2half_rn(v.y);
    b.x = __float2half_rn(v.z); b.y = __float2half_rn(v.w);
    ((__half2*)dst)[i * 2]     = a;
    ((__half2*)dst)[i * 2 + 1] = b;
}

// ---------------------------------------------------------------------------
extern "C" void kernel_launch(void* const* d_in, const int* in_sizes, int n_in,
                              void* d_out, int out_size)
{
    const float* token = (const float*)d_in[0];
    const float* W1    = (const float*)d_in[1];
    const float* W2    = (const float*)d_in[2];
    const float* W3    = (const float*)d_in[3];
    float*       out   = (float*)d_out;

    __half *th, *w12h, *w3h, *qk, *vt, *ss;
    float* rs;
    cudaGetSymbolAddress((void**)&th,   g_t);
    cudaGetSymbolAddress((void**)&w12h, g_w12h);
    cudaGetSymbolAddress((void**)&w3h,  g_w3h);
    cudaGetSymbolAddress((void**)&qk,   g_qk);
    cudaGetSymbolAddress((void**)&vt,   g_vt);
    cudaGetSymbolAddress((void**)&ss,   g_s);
    cudaGetSymbolAddress((void**)&rs,   g_rs);

    cudaFuncSetAttribute((const void*)mma_gemm<1>, cudaFuncAttributeMaxDynamicSharedMemorySize, SMEM_BYTES);
    cudaFuncSetAttribute((const void*)mma_gemm<2>, cudaFuncAttributeMaxDynamicSharedMemorySize, SMEM_BYTES);
    cudaFuncSetAttribute((const void*)mma_gemm<3>, cudaFuncAttributeMaxDynamicSharedMemorySize, SMEM_BYTES);

    // 1. conversions + rowsum zeroing (single launch)
    conv_kernel<<<(TOK_N4 + 3 * W_N4 + RS_N4 + 255) / 256, 256>>>(
        token, W1, W2, W3, th, w12h, w3h, rs);

    // 2. [Q|K] = token @ [W1;W2]^T -> fp16, [16384, 1024]
    mma_gemm<2><<<dim3(2 * DD / 128, BB * SS / 128, 1), 256, SMEM_BYTES>>>(
        th, DD, 0, w12h, DD, 0, nullptr, qk, nullptr, 2 * DD, 0, DD);
    // 3. VT = W3 @ token^T -> fp16  [512, 16384]
    mma_gemm<2><<<dim3(BB * SS / 128, DD / 128, 1), 256, SMEM_BYTES>>>(
        w3h, DD, 0, th, DD, 0, nullptr, vt, nullptr, BB * SS, 0, DD);
    // 4. E = exp(scale * Q @ K^T) per batch -> fp16, + row sums
    mma_gemm<3><<<dim3(SS / 128, SS / 128, BB), 256, SMEM_BYTES>>>(
        qk, 2 * DD, (long long)SS * 2 * DD, qk + DD, 2 * DD, (long long)SS * 2 * DD,
        nullptr, ss, rs, SS, (long long)SS * SS, DD);
    // 5. out = (E @ VT^T) / rowsum per batch -> fp32
    mma_gemm<1><<<dim3(DD / 128, SS / 128, BB), 256, SMEM_BYTES>>>(
        ss, SS, (long long)SS * SS, vt, BB * SS, (long long)SS,
        out, nullptr, rs, DD, (long long)SS * DD, SS);
}